// round 14
// baseline (speedup 1.0000x reference)
#include <cuda_runtime.h>
#include <cuda_fp16.h>
#include <cstdint>

#define B_    32
#define C_    256
#define L_    336
#define O_    96
#define KC_   4
#define NL_   2
#define DFF_  1024
#define KPAD  384              // L_ padded for k-blocking AND ffn2 n staging
#define PROWS 268
#define NGRP  67
#define MGRP  134              // 64-row m-groups (prow pairs)
#define MTOT  (PROWS * 32)     // 8576 rows (prow*32 + b)
#define NSPLIT 3               // FFN2 split-K factor

// ------------------------- device scratch -------------------------
__device__ float  g_Z[(size_t)MTOT * L_];                // residual stream fp32
__device__ __half g_Za[(size_t)MTOT * KPAD];             // z as single fp16 digit
__device__ __half g_Ha[(size_t)MTOT * DFF_];             // hidden as single fp16 digit
__device__ __half g_W1T[(size_t)KC_ * NL_ * DFF_ * KPAD];  // [kl][n][k] 1 digit
__device__ __half g_W2T[(size_t)KC_ * NL_ * KPAD * DFF_];  // [kl][n(384)][d]
__device__ float g_mean[MTOT];
__device__ float g_std[MTOT];
__device__ int   g_chan[PROWS];
__device__ int   g_clusprow[PROWS];
__device__ int   g_clusgrp[NGRP];
__device__ int   g_cnt2[NL_ * MGRP * 3];                 // split-K completion counters

// ------------------------- PTX helpers -----------------------------
__device__ __forceinline__ void ldsm4(uint32_t* r, uint32_t addr) {
    asm volatile("ldmatrix.sync.aligned.m8n8.x4.shared.b16 {%0,%1,%2,%3}, [%4];"
                 : "=r"(r[0]), "=r"(r[1]), "=r"(r[2]), "=r"(r[3]) : "r"(addr));
}
__device__ __forceinline__ void mma16816(float* d, const uint32_t* a,
                                         uint32_t b0, uint32_t b1) {
    asm volatile("mma.sync.aligned.m16n8k16.row.col.f32.f16.f16.f32 "
                 "{%0,%1,%2,%3}, {%4,%5,%6,%7}, {%8,%9}, {%0,%1,%2,%3};"
                 : "+f"(d[0]), "+f"(d[1]), "+f"(d[2]), "+f"(d[3])
                 : "r"(a[0]), "r"(a[1]), "r"(a[2]), "r"(a[3]), "r"(b0), "r"(b1));
}
__device__ __forceinline__ void cp_async16(uint32_t dst, const void* src) {
    asm volatile("cp.async.cg.shared.global [%0], [%1], 16;" :: "r"(dst), "l"(src));
}
__device__ __forceinline__ void cp_commit() { asm volatile("cp.async.commit_group;"); }
template <int N> __device__ __forceinline__ void cp_wait_n() {
    asm volatile("cp.async.wait_group %0;" :: "n"(N));
}

// ------------------------- prep: bucket channels + zero counters ----
__global__ void prep_kernel(const int* __restrict__ assign) {
    __shared__ int sa[C_];
    __shared__ int cnt[KC_];
    __shared__ int base[KC_ + 1];
    int t = threadIdx.x;
    for (int i = t; i < NL_ * MGRP * 3; i += 256) g_cnt2[i] = 0;
    if (t < KC_) cnt[t] = 0;
    __syncthreads();
    if (t < C_) {
        int k = assign[t];
        k = min(max(k, 0), KC_ - 1);
        sa[t] = k;
        atomicAdd(&cnt[k], 1);
    }
    __syncthreads();
    if (t == 0) {
        base[0] = 0;
        for (int k = 0; k < KC_; k++) base[k + 1] = base[k] + ((cnt[k] + 3) & ~3);
    }
    __syncthreads();
    for (int p = t; p < PROWS; p += blockDim.x) {
        int kk = 0;
        for (int k = 0; k < KC_; k++) if (p >= base[k + 1]) kk = k + 1;
        if (kk >= KC_) kk = 0;
        g_clusprow[p] = kk;
        g_chan[p] = -1;
    }
    __syncthreads();   // defaults visible before real channel writes
    if (t < C_) {
        int k = sa[t];
        int rank = 0;
        for (int c = 0; c < t; c++) rank += (sa[c] == k);
        g_chan[base[k] + rank] = t;
    }
    if (t < NGRP) {
        int p = t * 4;
        int kk = 0;
        for (int k = 0; k < KC_; k++) if (p >= base[k + 1]) kk = k + 1;
        if (kk >= KC_) kk = 0;
        g_clusgrp[t] = kk;
    }
}

// ------------------------- merged weight transpose + fp16 ----------
// z < 8:  W1 [kl][336][1024] -> W1T [kl][1024][384]
// z >= 8: W2 [kl][1024][336] -> W2T [kl][384][1024]
__global__ void convW_kernel(const float* __restrict__ W1,
                             const float* __restrict__ W2) {
    __shared__ float tile[32][33];
    int bz = blockIdx.z;
    int tx = threadIdx.x, ty = threadIdx.y;
    if (bz < KC_ * NL_) {
        int kl = bz;
        int n0 = blockIdx.x * 32, k0 = blockIdx.y * 32;
        const float* src = W1 + (size_t)kl * L_ * DFF_;
        for (int r = ty; r < 32; r += 8) {
            int k = k0 + r;
            tile[r][tx] = (k < L_) ? src[(size_t)k * DFF_ + n0 + tx] : 0.f;
        }
        __syncthreads();
        for (int r = ty; r < 32; r += 8) {
            int n = n0 + r, k = k0 + tx;
            g_W1T[((size_t)kl * DFF_ + n) * KPAD + k] = __float2half_rn(tile[tx][r]);
        }
    } else {
        int kl = bz - KC_ * NL_;
        int d0 = blockIdx.x * 32, n0 = blockIdx.y * 32;
        const float* src = W2 + (size_t)kl * DFF_ * L_;
        for (int r = ty; r < 32; r += 8) {
            int n = n0 + tx;
            tile[r][tx] = (n < L_) ? src[(size_t)(d0 + r) * L_ + n] : 0.f;
        }
        __syncthreads();
        for (int r = ty; r < 32; r += 8) {
            int n = n0 + r, d = d0 + tx;
            g_W2T[((size_t)kl * KPAD + n) * DFF_ + d] = __float2half_rn(tile[tx][r]);
        }
    }
}

// ------------------------- RevIN normalize (warp per row) -----------
__global__ void revin_kernel(const float* __restrict__ x,
                             const float* __restrict__ rev_w,
                             const float* __restrict__ rev_b) {
    int r = blockIdx.x * 8 + (threadIdx.x >> 5);   // 1072 blocks x 8 warps = 8576
    int lane = threadIdx.x & 31;
    int prow = r >> 5, b = r & 31;
    int c = g_chan[prow];
    float* zr = g_Z + (size_t)r * L_;
    __half* za = g_Za + (size_t)r * KPAD;

    if (c < 0) {
        for (int i = lane; i < L_; i += 32) zr[i] = 0.f;
        for (int i = lane; i < KPAD; i += 32) za[i] = __float2half(0.f);
        if (lane == 0) { g_mean[r] = 0.f; g_std[r] = 1.f; }
        return;
    }
    const float* xr = x + ((size_t)b * C_ + c) * L_;
    float v[11];
    float s = 0.f;
    #pragma unroll
    for (int j = 0; j < 11; j++) {
        int i = lane + j * 32;
        v[j] = (i < L_) ? xr[i] : 0.f;
        s += v[j];
    }
    #pragma unroll
    for (int o = 16; o > 0; o >>= 1) s += __shfl_xor_sync(0xffffffffu, s, o);
    float mean = s * (1.0f / L_);

    float vs = 0.f;
    #pragma unroll
    for (int j = 0; j < 11; j++) {
        int i = lane + j * 32;
        float d = v[j] - mean;
        vs += (i < L_) ? d * d : 0.f;
    }
    #pragma unroll
    for (int o = 16; o > 0; o >>= 1) vs += __shfl_xor_sync(0xffffffffu, vs, o);
    float stdv = sqrtf(vs * (1.0f / L_) + 1e-5f);

    float w  = rev_w[c], rb = rev_b[c];
    float rs = w / stdv;
    #pragma unroll
    for (int j = 0; j < 11; j++) {
        int i = lane + j * 32;
        if (i < L_) {
            float y = (v[j] - mean) * rs + rb;
            zr[i] = y;
            za[i] = __float2half_rn(y);
        }
    }
    for (int i = L_ + lane; i < KPAD; i += 32) za[i] = __float2half(0.f);
    if (lane == 0) { g_mean[r] = mean; g_std[r] = stdv; }
}

// ------------------------- HMMA FFN GEMMs --------------------------
// Single fp16 digit both sides, 1 MMA per k=16 chunk.
// 128 thr = 4 warps (2m x 2n), k-block 32, double buffer, 4 CTAs/SM.
// FFN1: NT=8, N-tile 128, K=336 (11 kb, half-trim on last).
// FFN2: NT=7, N-tile 112, split-K3 (11/11/10 kb), fp32 atomic reduce into
//       g_Z; last-arriving CTA per tile converts to fp16 g_Za.
#define A_TILE_B 5120                   // 64*80
#define B_TILE_B 10240                  // 128*80
#define BUF_B    (A_TILE_B + B_TILE_B)  // 15360
#define FFN_SMEM (2 * BUF_B)            // 30720

template <bool IS1>
__global__ __launch_bounds__(128, 4) void ffn_mma(const float* __restrict__ bias, int layer) {
    constexpr int NT   = IS1 ? 8 : 7;              // n-frags per warp
    constexpr int WN   = NT * 8;                   // warp n extent (64 / 56)
    constexpr int ASTR = IS1 ? KPAD : DFF_;
    constexpr int BSTR = IS1 ? KPAD : DFF_;

    extern __shared__ char smem[];
    uint32_t sb = (uint32_t)__cvta_generic_to_shared(smem);
    const int tid  = threadIdx.x;
    const int wid  = tid >> 5, lane = tid & 31;
    const int warp_m = wid & 1;
    const int warp_n = wid >> 1;

    const int n0 = blockIdx.x * (2 * WN);
    const int m0 = blockIdx.y * 64;
    const int kl = g_clusprow[blockIdx.y * 2] * NL_ + layer;
    const int ksplit = IS1 ? 0 : blockIdx.z;
    const int kbase  = ksplit * 11;
    const int nb     = IS1 ? 11 : ((ksplit == 2) ? 10 : 11);

    const __half* Aa0 = (IS1 ? g_Za : g_Ha) + (size_t)m0 * ASTR;
    const __half* Ba0 = (IS1 ? g_W1T : g_W2T) +
                        ((size_t)kl * (IS1 ? DFF_ : KPAD) + n0) * BSTR;
    const float* bp = bias + (size_t)kl * (IS1 ? DFF_ : L_);

    auto stage = [&](int buf, int kb) {
        uint32_t base = sb + buf * BUF_B;
        #pragma unroll
        for (int j = 0; j < 2; j++) {                 // A: 256 chunks
            int idx = tid + j * 128;
            int row = idx >> 2, c = idx & 3;
            uint32_t d = base + (uint32_t)(row * 80 + c * 16);
            size_t s = (size_t)row * ASTR + kb * 32 + c * 8;
            cp_async16(d, Aa0 + s);
        }
        #pragma unroll
        for (int j = 0; j < 4; j++) {                 // B: 512 chunks
            int idx = tid + j * 128;
            int row = idx >> 2, c = idx & 3;
            uint32_t d = base + A_TILE_B + (uint32_t)(row * 80 + c * 16);
            size_t s = (size_t)row * BSTR + kb * 32 + c * 8;
            cp_async16(d, Ba0 + s);
        }
        cp_commit();
    };

    float acc[2][NT][4];
    #pragma unroll
    for (int mt = 0; mt < 2; mt++)
        #pragma unroll
        for (int nt = 0; nt < NT; nt++)
            #pragma unroll
            for (int j = 0; j < 4; j++) acc[mt][nt][j] = 0.f;

    stage(0, kbase + 0);
    stage(1, kbase + 1);

    const uint32_t aoff0 = (uint32_t)((warp_m * 32 + (lane & 15)) * 80 + ((lane >> 4) * 16));
    const int g = lane >> 3;
    const uint32_t boffB = (uint32_t)((warp_n * WN + (g >> 1) * 8 + (lane & 7)) * 80 + (g & 1) * 16);

    #pragma unroll 1
    for (int lb = 0; lb < nb; lb++) {
        if (lb + 1 < nb) cp_wait_n<1>(); else cp_wait_n<0>();
        __syncthreads();
        uint32_t bufb = sb + (lb & 1) * BUF_B;

        #pragma unroll
        for (int ks = 0; ks < 2; ks++) {
            // FFN1 k-trim: k 336..351 are zero pad; skip the last half-block
            if (IS1 && lb == 10 && ks == 1) continue;
            uint32_t ah[2][4];
            #pragma unroll
            for (int mt = 0; mt < 2; mt++) {
                uint32_t aoff = aoff0 + (uint32_t)(mt * 16 * 80 + ks * 32);
                ldsm4(ah[mt], bufb + aoff);
            }
            #pragma unroll
            for (int pq = 0; pq < 4; pq++) {
                uint32_t bh[4];
                uint32_t boff = boffB + (uint32_t)(pq * 16 * 80 + ks * 32);
                ldsm4(bh, bufb + A_TILE_B + boff);
                #pragma unroll
                for (int half = 0; half < 2; half++) {
                    int nt = 2 * pq + half;
                    if (nt < NT) {
                        #pragma unroll
                        for (int mt = 0; mt < 2; mt++)
                            mma16816(acc[mt][nt], ah[mt], bh[2 * half], bh[2 * half + 1]);
                    }
                }
            }
        }
        __syncthreads();
        if (lb + 2 < nb) stage(lb & 1, kbase + lb + 2);
    }

    // ---- epilogue ----
    const int gq = lane >> 2, tq = lane & 3;
    #pragma unroll
    for (int mt = 0; mt < 2; mt++) {
        int rA = m0 + warp_m * 32 + mt * 16 + gq;
        int rB = rA + 8;
        #pragma unroll
        for (int nt = 0; nt < NT; nt++) {
            int col = n0 + warp_n * WN + nt * 8 + tq * 2;
            if (IS1) {
                float2 bv = *(const float2*)&bp[col];
                float y0 = fmaxf(acc[mt][nt][0] + bv.x, 0.f);
                float y1 = fmaxf(acc[mt][nt][1] + bv.y, 0.f);
                float y2 = fmaxf(acc[mt][nt][2] + bv.x, 0.f);
                float y3 = fmaxf(acc[mt][nt][3] + bv.y, 0.f);
                __half2 pa; pa.x = __float2half_rn(y0); pa.y = __float2half_rn(y1);
                __half2 pb; pb.x = __float2half_rn(y2); pb.y = __float2half_rn(y3);
                *(__half2*)(g_Ha + (size_t)rA * DFF_ + col) = pa;
                *(__half2*)(g_Ha + (size_t)rB * DFF_ + col) = pb;
            } else {
                // split-K partial: atomic reduce into fp32 residual
                float bx = (ksplit == 0) ? bp[col] : 0.f;
                float by = (ksplit == 0) ? bp[col + 1] : 0.f;
                atomicAdd(&g_Z[(size_t)rA * L_ + col],     acc[mt][nt][0] + bx);
                atomicAdd(&g_Z[(size_t)rA * L_ + col + 1], acc[mt][nt][1] + by);
                atomicAdd(&g_Z[(size_t)rB * L_ + col],     acc[mt][nt][2] + bx);
                atomicAdd(&g_Z[(size_t)rB * L_ + col + 1], acc[mt][nt][3] + by);
            }
        }
    }

    if (!IS1) {
        // completion counter; last CTA converts tile to fp16 g_Za
        __threadfence();
        __syncthreads();
        __shared__ int done;
        if (tid == 0)
            done = atomicAdd(&g_cnt2[layer * MGRP * 3 + blockIdx.y * 3 + blockIdx.x], 1);
        __syncthreads();
        if (done == NSPLIT - 1) {
            for (int i = tid; i < 64 * 112; i += 128) {
                int r = i / 112, cc = i - r * 112;
                int grow = m0 + r, gcol = n0 + cc;
                float z = __ldcg(&g_Z[(size_t)grow * L_ + gcol]);
                g_Za[(size_t)grow * KPAD + gcol] = __float2half_rn(z);
            }
        }
    }
}

// ------------------------- head + denorm + transpose ----------------
__global__ void head_kernel(const float* __restrict__ Wh,
                            const float* __restrict__ bh,
                            const float* __restrict__ rev_w,
                            const float* __restrict__ rev_b,
                            float* __restrict__ out) {
    int prow = blockIdx.x;
    int c = g_chan[prow];
    if (c < 0) return;
    int kc = g_clusprow[prow];

    __shared__ __align__(16) float Zs[32][65];
    __shared__ __align__(16) float Ws[64][96];

    int tid = threadIdx.x;       // 256
    int row = tid & 31;
    int cg  = tid >> 5;
    float acc[12];
    #pragma unroll
    for (int j = 0; j < 12; j++) acc[j] = 0.f;

    const float* Whk = Wh + (size_t)kc * L_ * O_;
    for (int l0 = 0; l0 < L_; l0 += 64) {
        int lc = min(64, L_ - l0);
        for (int i = tid; i < 32 * 64; i += 256) {
            int rr = i >> 6, ll = i & 63;
            Zs[rr][ll] = (ll < lc) ? g_Z[(size_t)(prow * 32 + rr) * L_ + l0 + ll] : 0.f;
        }
        for (int i = tid; i < 64 * 96; i += 256) {
            int ll = i / 96, o = i - ll * 96;
            Ws[ll][o] = (ll < lc) ? Whk[(size_t)(l0 + ll) * O_ + o] : 0.f;
        }
        __syncthreads();
        #pragma unroll 8
        for (int ll = 0; ll < 64; ll++) {
            float a = Zs[row][ll];
            float4 w0 = *(const float4*)&Ws[ll][cg * 12];
            float4 w1 = *(const float4*)&Ws[ll][cg * 12 + 4];
            float4 w2 = *(const float4*)&Ws[ll][cg * 12 + 8];
            acc[0]  += a * w0.x; acc[1]  += a * w0.y; acc[2]  += a * w0.z; acc[3]  += a * w0.w;
            acc[4]  += a * w1.x; acc[5]  += a * w1.y; acc[6]  += a * w1.z; acc[7]  += a * w1.w;
            acc[8]  += a * w2.x; acc[9]  += a * w2.y; acc[10] += a * w2.z; acc[11] += a * w2.w;
        }
        __syncthreads();
    }

    int rg = prow * 32 + row;
    float mean = g_mean[rg], stdv = g_std[rg];
    float w = rev_w[c], rb = rev_b[c];
    float scale = stdv / w;
    #pragma unroll
    for (int j = 0; j < 12; j++) {
        int o = cg * 12 + j;
        float y = acc[j] + bh[kc * O_ + o];
        out[((size_t)row * O_ + o) * C_ + c] = (y - rb) * scale + mean;
    }
}

// ------------------------- launch ----------------------------------
extern "C" void kernel_launch(void* const* d_in, const int* in_sizes, int n_in,
                              void* d_out, int out_size) {
    const float* x     = (const float*)d_in[0];
    const float* rev_w = (const float*)d_in[1];
    const float* rev_b = (const float*)d_in[2];
    const float* W1    = (const float*)d_in[3];
    const float* b1    = (const float*)d_in[4];
    const float* W2    = (const float*)d_in[5];
    const float* b2    = (const float*)d_in[6];
    const float* Wh    = (const float*)d_in[7];
    const float* bh    = (const float*)d_in[8];
    const int*   assign = (const int*)d_in[9];
    float* out = (float*)d_out;

    cudaFuncSetAttribute(ffn_mma<true>,  cudaFuncAttributeMaxDynamicSharedMemorySize, FFN_SMEM);
    cudaFuncSetAttribute(ffn_mma<false>, cudaFuncAttributeMaxDynamicSharedMemorySize, FFN_SMEM);

    prep_kernel<<<1, 256>>>(assign);
    convW_kernel<<<dim3(32, 12, 2 * KC_ * NL_), dim3(32, 8)>>>(W1, W2);
    revin_kernel<<<MTOT / 8, 256>>>(x, rev_w, rev_b);
    for (int l = 0; l < NL_; l++) {
        ffn_mma<true ><<<dim3(DFF_ / 128, MGRP), 128, FFN_SMEM>>>(b1, l);      // 8 x 134
        ffn_mma<false><<<dim3(3, MGRP, NSPLIT), 128, FFN_SMEM>>>(b2, l);       // 3 x 134 x 3
    }
    head_kernel<<<PROWS, 256>>>(Wh, bh, rev_w, rev_b, out);
}

// round 15
// speedup vs baseline: 1.2252x; 1.2252x over previous
#include <cuda_runtime.h>
#include <cuda_fp16.h>
#include <cstdint>

#define B_    32
#define C_    256
#define L_    336
#define O_    96
#define KC_   4
#define NL_   2
#define DFF_  1024
#define KPAD  384              // L_ padded for k-blocking AND ffn2 n staging
#define PROWS 268
#define NGRP  67
#define MGRP  134              // 64-row m-groups (prow pairs)
#define MTOT  (PROWS * 32)     // 8576 rows (prow*32 + b)

// ------------------------- device scratch -------------------------
__device__ float  g_Z[(size_t)MTOT * L_];                // residual stream fp32
__device__ __half g_Za[(size_t)MTOT * KPAD];             // z as single fp16 digit
__device__ __half g_Ha[(size_t)MTOT * DFF_];             // hidden as single fp16 digit
__device__ __half g_W1T[(size_t)KC_ * NL_ * DFF_ * KPAD];  // [kl][n][k] 1 digit
__device__ __half g_W2T[(size_t)KC_ * NL_ * KPAD * DFF_];  // [kl][n(384)][d]
__device__ float g_mean[MTOT];
__device__ float g_std[MTOT];
__device__ int   g_chan[PROWS];
__device__ int   g_clusprow[PROWS];
__device__ int   g_clusgrp[NGRP];

// ------------------------- PTX helpers -----------------------------
__device__ __forceinline__ void ldsm4(uint32_t* r, uint32_t addr) {
    asm volatile("ldmatrix.sync.aligned.m8n8.x4.shared.b16 {%0,%1,%2,%3}, [%4];"
                 : "=r"(r[0]), "=r"(r[1]), "=r"(r[2]), "=r"(r[3]) : "r"(addr));
}
__device__ __forceinline__ void mma16816(float* d, const uint32_t* a,
                                         uint32_t b0, uint32_t b1) {
    asm volatile("mma.sync.aligned.m16n8k16.row.col.f32.f16.f16.f32 "
                 "{%0,%1,%2,%3}, {%4,%5,%6,%7}, {%8,%9}, {%0,%1,%2,%3};"
                 : "+f"(d[0]), "+f"(d[1]), "+f"(d[2]), "+f"(d[3])
                 : "r"(a[0]), "r"(a[1]), "r"(a[2]), "r"(a[3]), "r"(b0), "r"(b1));
}
__device__ __forceinline__ void cp_async16(uint32_t dst, const void* src) {
    asm volatile("cp.async.cg.shared.global [%0], [%1], 16;" :: "r"(dst), "l"(src));
}
__device__ __forceinline__ void cp_commit() { asm volatile("cp.async.commit_group;"); }
template <int N> __device__ __forceinline__ void cp_wait_n() {
    asm volatile("cp.async.wait_group %0;" :: "n"(N));
}

// ------------------------- prep: bucket channels by cluster --------
__global__ void prep_kernel(const int* __restrict__ assign) {
    __shared__ int sa[C_];
    __shared__ int cnt[KC_];
    __shared__ int base[KC_ + 1];
    int t = threadIdx.x;
    if (t < KC_) cnt[t] = 0;
    __syncthreads();
    if (t < C_) {
        int k = assign[t];
        k = min(max(k, 0), KC_ - 1);
        sa[t] = k;
        atomicAdd(&cnt[k], 1);
    }
    __syncthreads();
    if (t == 0) {
        base[0] = 0;
        for (int k = 0; k < KC_; k++) base[k + 1] = base[k] + ((cnt[k] + 3) & ~3);
    }
    __syncthreads();
    for (int p = t; p < PROWS; p += blockDim.x) {
        int kk = 0;
        for (int k = 0; k < KC_; k++) if (p >= base[k + 1]) kk = k + 1;
        if (kk >= KC_) kk = 0;
        g_clusprow[p] = kk;
        g_chan[p] = -1;
    }
    __syncthreads();   // defaults visible before real channel writes
    if (t < C_) {
        int k = sa[t];
        int rank = 0;
        for (int c = 0; c < t; c++) rank += (sa[c] == k);
        g_chan[base[k] + rank] = t;
    }
    if (t < NGRP) {
        int p = t * 4;
        int kk = 0;
        for (int k = 0; k < KC_; k++) if (p >= base[k + 1]) kk = k + 1;
        if (kk >= KC_) kk = 0;
        g_clusgrp[t] = kk;
    }
}

// ------------------------- merged weight transpose + fp16 ----------
// z < 8:  W1 [kl][336][1024] -> W1T [kl][1024][384]
// z >= 8: W2 [kl][1024][336] -> W2T [kl][384][1024]
__global__ void convW_kernel(const float* __restrict__ W1,
                             const float* __restrict__ W2) {
    __shared__ float tile[32][33];
    int bz = blockIdx.z;
    int tx = threadIdx.x, ty = threadIdx.y;
    if (bz < KC_ * NL_) {
        int kl = bz;
        int n0 = blockIdx.x * 32, k0 = blockIdx.y * 32;
        const float* src = W1 + (size_t)kl * L_ * DFF_;
        for (int r = ty; r < 32; r += 8) {
            int k = k0 + r;
            tile[r][tx] = (k < L_) ? src[(size_t)k * DFF_ + n0 + tx] : 0.f;
        }
        __syncthreads();
        for (int r = ty; r < 32; r += 8) {
            int n = n0 + r, k = k0 + tx;
            g_W1T[((size_t)kl * DFF_ + n) * KPAD + k] = __float2half_rn(tile[tx][r]);
        }
    } else {
        int kl = bz - KC_ * NL_;
        int d0 = blockIdx.x * 32, n0 = blockIdx.y * 32;
        const float* src = W2 + (size_t)kl * DFF_ * L_;
        for (int r = ty; r < 32; r += 8) {
            int n = n0 + tx;
            tile[r][tx] = (n < L_) ? src[(size_t)(d0 + r) * L_ + n] : 0.f;
        }
        __syncthreads();
        for (int r = ty; r < 32; r += 8) {
            int n = n0 + r, d = d0 + tx;
            g_W2T[((size_t)kl * KPAD + n) * DFF_ + d] = __float2half_rn(tile[tx][r]);
        }
    }
}

// ------------------------- RevIN normalize (warp per row) -----------
__global__ void revin_kernel(const float* __restrict__ x,
                             const float* __restrict__ rev_w,
                             const float* __restrict__ rev_b) {
    int r = blockIdx.x * 8 + (threadIdx.x >> 5);   // 1072 blocks x 8 warps = 8576
    int lane = threadIdx.x & 31;
    int prow = r >> 5, b = r & 31;
    int c = g_chan[prow];
    float* zr = g_Z + (size_t)r * L_;
    __half* za = g_Za + (size_t)r * KPAD;

    if (c < 0) {
        for (int i = lane; i < L_; i += 32) zr[i] = 0.f;
        for (int i = lane; i < KPAD; i += 32) za[i] = __float2half(0.f);
        if (lane == 0) { g_mean[r] = 0.f; g_std[r] = 1.f; }
        return;
    }
    const float* xr = x + ((size_t)b * C_ + c) * L_;
    float v[11];
    float s = 0.f;
    #pragma unroll
    for (int j = 0; j < 11; j++) {
        int i = lane + j * 32;
        v[j] = (i < L_) ? xr[i] : 0.f;
        s += v[j];
    }
    #pragma unroll
    for (int o = 16; o > 0; o >>= 1) s += __shfl_xor_sync(0xffffffffu, s, o);
    float mean = s * (1.0f / L_);

    float vs = 0.f;
    #pragma unroll
    for (int j = 0; j < 11; j++) {
        int i = lane + j * 32;
        float d = v[j] - mean;
        vs += (i < L_) ? d * d : 0.f;
    }
    #pragma unroll
    for (int o = 16; o > 0; o >>= 1) vs += __shfl_xor_sync(0xffffffffu, vs, o);
    float stdv = sqrtf(vs * (1.0f / L_) + 1e-5f);

    float w  = rev_w[c], rb = rev_b[c];
    float rs = w / stdv;
    #pragma unroll
    for (int j = 0; j < 11; j++) {
        int i = lane + j * 32;
        if (i < L_) {
            float y = (v[j] - mean) * rs + rb;
            zr[i] = y;
            za[i] = __float2half_rn(y);
        }
    }
    for (int i = L_ + lane; i < KPAD; i += 32) za[i] = __float2half(0.f);
    if (lane == 0) { g_mean[r] = mean; g_std[r] = stdv; }
}

// ------------------------- HMMA FFN GEMMs --------------------------
// Single fp16 digit both sides, 1 MMA per k=16 chunk.
// 128 thr = 4 warps (2m x 2n), k-block 32, 3-STAGE cp.async ring with a
// SINGLE __syncthreads per k-block; staging issued BEFORE compute so the
// async copy overlaps the whole MMA phase. 4 CTAs/SM (3x15KB smem).
// FFN1: NT=8, N-tile 128, K=336 (11 kb, half-trim on last).
// FFN2: NT=7, N-tile 112 (3x112=336, zero N-pad), K=1024 (32 kb).
#define A_TILE_B 5120                   // 64*80
#define B_TILE_B 10240                  // 128*80
#define BUF_B    (A_TILE_B + B_TILE_B)  // 15360
#define FFN_SMEM (3 * BUF_B)            // 46080

template <bool IS1>
__global__ __launch_bounds__(128, 4) void ffn_mma(const float* __restrict__ bias, int layer) {
    constexpr int NB   = IS1 ? 11 : (DFF_ / 32);   // 11 : 32 k-blocks
    constexpr int NT   = IS1 ? 8 : 7;              // n-frags per warp
    constexpr int WN   = NT * 8;                   // warp n extent (64 / 56)
    constexpr int ASTR = IS1 ? KPAD : DFF_;
    constexpr int BSTR = IS1 ? KPAD : DFF_;

    extern __shared__ char smem[];
    uint32_t sb = (uint32_t)__cvta_generic_to_shared(smem);
    const int tid  = threadIdx.x;
    const int wid  = tid >> 5, lane = tid & 31;
    const int warp_m = wid & 1;
    const int warp_n = wid >> 1;

    const int n0 = blockIdx.x * (2 * WN);
    const int m0 = blockIdx.y * 64;
    const int kl = g_clusprow[blockIdx.y * 2] * NL_ + layer;

    const __half* Aa0 = (IS1 ? g_Za : g_Ha) + (size_t)m0 * ASTR;
    const __half* Ba0 = (IS1 ? g_W1T : g_W2T) +
                        ((size_t)kl * (IS1 ? DFF_ : KPAD) + n0) * BSTR;
    const float* bp = bias + (size_t)kl * (IS1 ? DFF_ : L_);

    auto stage = [&](int buf, int kb) {
        uint32_t base = sb + buf * BUF_B;
        #pragma unroll
        for (int j = 0; j < 2; j++) {                 // A: 256 chunks
            int idx = tid + j * 128;
            int row = idx >> 2, c = idx & 3;
            uint32_t d = base + (uint32_t)(row * 80 + c * 16);
            size_t s = (size_t)row * ASTR + kb * 32 + c * 8;
            cp_async16(d, Aa0 + s);
        }
        #pragma unroll
        for (int j = 0; j < 4; j++) {                 // B: 512 chunks
            int idx = tid + j * 128;
            int row = idx >> 2, c = idx & 3;
            uint32_t d = base + A_TILE_B + (uint32_t)(row * 80 + c * 16);
            size_t s = (size_t)row * BSTR + kb * 32 + c * 8;
            cp_async16(d, Ba0 + s);
        }
        cp_commit();
    };

    float acc[2][NT][4];
    #pragma unroll
    for (int mt = 0; mt < 2; mt++)
        #pragma unroll
        for (int nt = 0; nt < NT; nt++)
            #pragma unroll
            for (int j = 0; j < 4; j++) acc[mt][nt][j] = 0.f;

    stage(0, 0);
    stage(1, 1);

    const uint32_t aoff0 = (uint32_t)((warp_m * 32 + (lane & 15)) * 80 + ((lane >> 4) * 16));
    const int g = lane >> 3;
    const uint32_t boffB = (uint32_t)((warp_n * WN + (g >> 1) * 8 + (lane & 7)) * 80 + (g & 1) * 16);

    int cbuf = 0, sbuf = 2;
    #pragma unroll 1
    for (int lb = 0; lb < NB; lb++) {
        if (lb + 1 < NB) cp_wait_n<1>(); else cp_wait_n<0>();
        __syncthreads();
        // stage k-block lb+2 into the buffer consumed at lb-1 (safe: all
        // warps passed the sync above after finishing iteration lb-1)
        if (lb + 2 < NB) {
            stage(sbuf, lb + 2);
            sbuf = (sbuf == 2) ? 0 : sbuf + 1;
        }
        uint32_t bufb = sb + cbuf * BUF_B;
        cbuf = (cbuf == 2) ? 0 : cbuf + 1;

        #pragma unroll
        for (int ks = 0; ks < 2; ks++) {
            // FFN1 k-trim: k 336..351 are zero pad; skip the last half-block
            if (IS1 && lb == 10 && ks == 1) continue;
            uint32_t ah[2][4];
            #pragma unroll
            for (int mt = 0; mt < 2; mt++) {
                uint32_t aoff = aoff0 + (uint32_t)(mt * 16 * 80 + ks * 32);
                ldsm4(ah[mt], bufb + aoff);
            }
            #pragma unroll
            for (int pq = 0; pq < 4; pq++) {
                uint32_t bh[4];
                uint32_t boff = boffB + (uint32_t)(pq * 16 * 80 + ks * 32);
                ldsm4(bh, bufb + A_TILE_B + boff);
                #pragma unroll
                for (int half = 0; half < 2; half++) {
                    int nt = 2 * pq + half;
                    if (nt < NT) {
                        #pragma unroll
                        for (int mt = 0; mt < 2; mt++)
                            mma16816(acc[mt][nt], ah[mt], bh[2 * half], bh[2 * half + 1]);
                    }
                }
            }
        }
    }

    // ---- epilogue ----
    const int gq = lane >> 2, tq = lane & 3;
    #pragma unroll
    for (int mt = 0; mt < 2; mt++) {
        int rA = m0 + warp_m * 32 + mt * 16 + gq;
        int rB = rA + 8;
        #pragma unroll
        for (int nt = 0; nt < NT; nt++) {
            int col = n0 + warp_n * WN + nt * 8 + tq * 2;
            if (IS1) {
                float2 bv = *(const float2*)&bp[col];
                float y0 = fmaxf(acc[mt][nt][0] + bv.x, 0.f);
                float y1 = fmaxf(acc[mt][nt][1] + bv.y, 0.f);
                float y2 = fmaxf(acc[mt][nt][2] + bv.x, 0.f);
                float y3 = fmaxf(acc[mt][nt][3] + bv.y, 0.f);
                __half2 pa; pa.x = __float2half_rn(y0); pa.y = __float2half_rn(y1);
                __half2 pb; pb.x = __float2half_rn(y2); pb.y = __float2half_rn(y3);
                *(__half2*)(g_Ha + (size_t)rA * DFF_ + col) = pa;
                *(__half2*)(g_Ha + (size_t)rB * DFF_ + col) = pb;
            } else {
                // NT=7 tiling: col <= 334 always (3*112 = 336 exact)
                float2 bv = *(const float2*)&bp[col];
                float2* zpA = (float2*)(g_Z + (size_t)rA * L_ + col);
                float2* zpB = (float2*)(g_Z + (size_t)rB * L_ + col);
                float2 zA = *zpA, zB = *zpB;
                float z0 = zA.x + acc[mt][nt][0] + bv.x;
                float z1 = zA.y + acc[mt][nt][1] + bv.y;
                float z2 = zB.x + acc[mt][nt][2] + bv.x;
                float z3 = zB.y + acc[mt][nt][3] + bv.y;
                *zpA = make_float2(z0, z1);
                *zpB = make_float2(z2, z3);
                __half2 pa; pa.x = __float2half_rn(z0); pa.y = __float2half_rn(z1);
                __half2 pb; pb.x = __float2half_rn(z2); pb.y = __float2half_rn(z3);
                *(__half2*)(g_Za + (size_t)rA * KPAD + col) = pa;
                *(__half2*)(g_Za + (size_t)rB * KPAD + col) = pb;
            }
        }
    }
}

// ------------------------- head + denorm + transpose ----------------
__global__ void head_kernel(const float* __restrict__ Wh,
                            const float* __restrict__ bh,
                            const float* __restrict__ rev_w,
                            const float* __restrict__ rev_b,
                            float* __restrict__ out) {
    int prow = blockIdx.x;
    int c = g_chan[prow];
    if (c < 0) return;
    int kc = g_clusprow[prow];

    __shared__ __align__(16) float Zs[32][65];
    __shared__ __align__(16) float Ws[64][96];

    int tid = threadIdx.x;       // 256
    int row = tid & 31;
    int cg  = tid >> 5;
    float acc[12];
    #pragma unroll
    for (int j = 0; j < 12; j++) acc[j] = 0.f;

    const float* Whk = Wh + (size_t)kc * L_ * O_;
    for (int l0 = 0; l0 < L_; l0 += 64) {
        int lc = min(64, L_ - l0);
        for (int i = tid; i < 32 * 64; i += 256) {
            int rr = i >> 6, ll = i & 63;
            Zs[rr][ll] = (ll < lc) ? g_Z[(size_t)(prow * 32 + rr) * L_ + l0 + ll] : 0.f;
        }
        for (int i = tid; i < 64 * 96; i += 256) {
            int ll = i / 96, o = i - ll * 96;
            Ws[ll][o] = (ll < lc) ? Whk[(size_t)(l0 + ll) * O_ + o] : 0.f;
        }
        __syncthreads();
        #pragma unroll 8
        for (int ll = 0; ll < 64; ll++) {
            float a = Zs[row][ll];
            float4 w0 = *(const float4*)&Ws[ll][cg * 12];
            float4 w1 = *(const float4*)&Ws[ll][cg * 12 + 4];
            float4 w2 = *(const float4*)&Ws[ll][cg * 12 + 8];
            acc[0]  += a * w0.x; acc[1]  += a * w0.y; acc[2]  += a * w0.z; acc[3]  += a * w0.w;
            acc[4]  += a * w1.x; acc[5]  += a * w1.y; acc[6]  += a * w1.z; acc[7]  += a * w1.w;
            acc[8]  += a * w2.x; acc[9]  += a * w2.y; acc[10] += a * w2.z; acc[11] += a * w2.w;
        }
        __syncthreads();
    }

    int rg = prow * 32 + row;
    float mean = g_mean[rg], stdv = g_std[rg];
    float w = rev_w[c], rb = rev_b[c];
    float scale = stdv / w;
    #pragma unroll
    for (int j = 0; j < 12; j++) {
        int o = cg * 12 + j;
        float y = acc[j] + bh[kc * O_ + o];
        out[((size_t)row * O_ + o) * C_ + c] = (y - rb) * scale + mean;
    }
}

// ------------------------- launch ----------------------------------
extern "C" void kernel_launch(void* const* d_in, const int* in_sizes, int n_in,
                              void* d_out, int out_size) {
    const float* x     = (const float*)d_in[0];
    const float* rev_w = (const float*)d_in[1];
    const float* rev_b = (const float*)d_in[2];
    const float* W1    = (const float*)d_in[3];
    const float* b1    = (const float*)d_in[4];
    const float* W2    = (const float*)d_in[5];
    const float* b2    = (const float*)d_in[6];
    const float* Wh    = (const float*)d_in[7];
    const float* bh    = (const float*)d_in[8];
    const int*   assign = (const int*)d_in[9];
    float* out = (float*)d_out;

    cudaFuncSetAttribute(ffn_mma<true>,  cudaFuncAttributeMaxDynamicSharedMemorySize, FFN_SMEM);
    cudaFuncSetAttribute(ffn_mma<false>, cudaFuncAttributeMaxDynamicSharedMemorySize, FFN_SMEM);

    prep_kernel<<<1, 256>>>(assign);
    convW_kernel<<<dim3(32, 12, 2 * KC_ * NL_), dim3(32, 8)>>>(W1, W2);
    revin_kernel<<<MTOT / 8, 256>>>(x, rev_w, rev_b);
    for (int l = 0; l < NL_; l++) {
        ffn_mma<true ><<<dim3(DFF_ / 128, MGRP), 128, FFN_SMEM>>>(b1, l);   // 8 x 134
        ffn_mma<false><<<dim3(3,          MGRP), 128, FFN_SMEM>>>(b2, l);   // 3 x 134
    }
    head_kernel<<<PROWS, 256>>>(Wh, bh, rev_w, rev_b, out);
}